// round 1
// baseline (speedup 1.0000x reference)
#include <cuda_runtime.h>

#define NUM_EXPERTS 8
#define DIM 1024
#define NT 256          // threads per CTA
#define F4 (DIM / 4)    // 256 float4 per vector

// Block reduction of NV partial sums (one per k). 256 threads = 8 warps.
// Warp-shuffle reduce, lane0 -> smem, then every thread sums the 8 warp
// results (broadcast LDS, conflict-free).
template <int NV>
__device__ __forceinline__ void block_reduce(float* p, float red[8][8],
                                             int warp, int lane) {
#pragma unroll
    for (int k = 0; k < NV; k++) {
        float s = p[k];
#pragma unroll
        for (int o = 16; o > 0; o >>= 1)
            s += __shfl_xor_sync(0xffffffffu, s, o);
        if (lane == 0) red[k][warp] = s;
    }
    __syncthreads();
#pragma unroll
    for (int k = 0; k < NV; k++) {
        float s = 0.0f;
#pragma unroll
        for (int w = 0; w < 8; w++) s += red[k][w];
        p[k] = s;
    }
    __syncthreads();  // protect smem reuse in next round
}

__global__ __launch_bounds__(NT) void gram_schmidt_kernel(
    const float* __restrict__ x, float* __restrict__ out) {
    const int b = blockIdx.x;
    const int t = threadIdx.x;
    const int warp = t >> 5;
    const int lane = t & 31;

    __shared__ float red[8][8];

    const float4* __restrict__ xin =
        reinterpret_cast<const float4*>(x + (size_t)b * NUM_EXPERTS * DIM);
    float4* __restrict__ xout =
        reinterpret_cast<float4*>(out + (size_t)b * NUM_EXPERTS * DIM);

    // Load all 8 expert vectors' slice into registers (coalesced float4).
    float4 v[NUM_EXPERTS];
#pragma unroll
    for (int i = 0; i < NUM_EXPERTS; i++) v[i] = xin[i * F4 + t];

    // ---- Normalize v0 ----
    {
        float p[1];
        p[0] = v[0].x * v[0].x + v[0].y * v[0].y + v[0].z * v[0].z +
               v[0].w * v[0].w;
        block_reduce<1>(p, red, warp, lane);
        float inv = rsqrtf(p[0]);
        v[0].x *= inv; v[0].y *= inv; v[0].z *= inv; v[0].w *= inv;
    }

    // ---- Classical Gram-Schmidt for i = 1..7 ----
#pragma unroll
    for (int i = 1; i < NUM_EXPERTS; i++) {
        float p[NUM_EXPERTS - 1];
        // coeff_k = v_i . basis_k for k < i
#pragma unroll
        for (int k = 0; k < NUM_EXPERTS - 1; k++) {
            if (k < i) {
                p[k] = v[i].x * v[k].x + v[i].y * v[k].y +
                       v[i].z * v[k].z + v[i].w * v[k].w;
            }
        }
        // Reduce exactly i values (dispatch to constant-NV instantiations).
        switch (i) {
            case 1: block_reduce<1>(p, red, warp, lane); break;
            case 2: block_reduce<2>(p, red, warp, lane); break;
            case 3: block_reduce<3>(p, red, warp, lane); break;
            case 4: block_reduce<4>(p, red, warp, lane); break;
            case 5: block_reduce<5>(p, red, warp, lane); break;
            case 6: block_reduce<6>(p, red, warp, lane); break;
            case 7: block_reduce<7>(p, red, warp, lane); break;
        }
        // w = v_i - sum_k coeff_k * basis_k
        float4 w = v[i];
#pragma unroll
        for (int k = 0; k < NUM_EXPERTS - 1; k++) {
            if (k < i) {
                w.x -= p[k] * v[k].x;
                w.y -= p[k] * v[k].y;
                w.z -= p[k] * v[k].z;
                w.w -= p[k] * v[k].w;
            }
        }
        // normalize w
        float q[1];
        q[0] = w.x * w.x + w.y * w.y + w.z * w.z + w.w * w.w;
        block_reduce<1>(q, red, warp, lane);
        float inv = rsqrtf(q[0]);
        v[i].x = w.x * inv;
        v[i].y = w.y * inv;
        v[i].z = w.z * inv;
        v[i].w = w.w * inv;
    }

    // ---- Store all 8 basis vectors (coalesced float4) ----
#pragma unroll
    for (int i = 0; i < NUM_EXPERTS; i++) xout[i * F4 + t] = v[i];
}

extern "C" void kernel_launch(void* const* d_in, const int* in_sizes, int n_in,
                              void* d_out, int out_size) {
    const float* x = (const float*)d_in[0];
    float* out = (float*)d_out;
    const int batch = in_sizes[0] / (NUM_EXPERTS * DIM);  // 8192
    gram_schmidt_kernel<<<batch, NT>>>(x, out);
}

// round 2
// speedup vs baseline: 1.1484x; 1.1484x over previous
#include <cuda_runtime.h>

#define NE 8
#define DIM 1024
#define NT 256
#define F4 (DIM / 4)
#define NG 36  // 8*9/2 lower-triangle entries

__device__ __host__ __forceinline__ constexpr int tri(int i, int j) {
    return i * (i + 1) / 2 + j;  // j <= i
}

__global__ __launch_bounds__(NT, 2) void gram_gs_kernel(
    const float* __restrict__ x, float* __restrict__ out) {
    const int b = blockIdx.x;
    const int t = threadIdx.x;
    const int warp = t >> 5;
    const int lane = t & 31;

    __shared__ float red[NG][8];

    const float4* __restrict__ xin =
        reinterpret_cast<const float4*>(x + (size_t)b * NE * DIM);
    float4* __restrict__ xout =
        reinterpret_cast<float4*>(out + (size_t)b * NE * DIM);

    // ---- Load all 8 expert slices (coalesced LDG.128, front-batched) ----
    float4 v[NE];
#pragma unroll
    for (int i = 0; i < NE; i++) v[i] = xin[i * F4 + t];

    // ---- Partial Gram matrix: 36 dot-product partials ----
    float g[NG];
#pragma unroll
    for (int i = 0; i < NE; i++) {
#pragma unroll
        for (int j = 0; j <= i; j++) {
            g[tri(i, j)] = v[i].x * v[j].x + v[i].y * v[j].y +
                           v[i].z * v[j].z + v[i].w * v[j].w;
        }
    }

    // ---- ONE block reduction of all 36 values ----
#pragma unroll
    for (int k = 0; k < NG; k++) {
        float s = g[k];
#pragma unroll
        for (int o = 16; o > 0; o >>= 1)
            s += __shfl_xor_sync(0xffffffffu, s, o);
        if (lane == 0) red[k][warp] = s;
    }
    __syncthreads();
#pragma unroll
    for (int k = 0; k < NG; k++) {
        float s = 0.0f;
#pragma unroll
        for (int w = 0; w < 8; w++) s += red[k][w];
        g[k] = s;
    }
    // (no smem reuse afterwards -> no second barrier needed)

    // ---- Gram-Schmidt in coefficient space (redundant per thread) ----
    // W is lower-triangular: basis_i = sum_{j<=i} W[i][j] * x_j
    float W[NG];
    W[tri(0, 0)] = rsqrtf(g[tri(0, 0)]);
    {
        // output row 0
        float w00 = W[tri(0, 0)];
        float4 o;
        o.x = w00 * v[0].x; o.y = w00 * v[0].y;
        o.z = w00 * v[0].z; o.w = w00 * v[0].w;
        xout[0 * F4 + t] = o;
    }

#pragma unroll
    for (int i = 1; i < NE; i++) {
        // c_k = x_i . basis_k = sum_{j<=k} W[k][j] * G[i][j]   (k < i)
        float c[NE];
#pragma unroll
        for (int k = 0; k < NE - 1; k++) {
            if (k < i) {
                float s = 0.0f;
#pragma unroll
                for (int j = 0; j < NE - 1; j++) {
                    if (j <= k) s += W[tri(k, j)] * g[tri(i, j)];
                }
                c[k] = s;
            }
        }
        // ||w||^2 = G_ii - sum_k c_k^2   (basis orthonormal)
        float n2 = g[tri(i, i)];
#pragma unroll
        for (int k = 0; k < NE - 1; k++) {
            if (k < i) n2 -= c[k] * c[k];
        }
        float inv = rsqrtf(n2);
        // W[i][j] = inv * (delta_ij - sum_{k=j..i-1} c_k W[k][j])
#pragma unroll
        for (int j = 0; j < NE - 1; j++) {
            if (j < i) {
                float s = 0.0f;
#pragma unroll
                for (int k = 0; k < NE - 1; k++) {
                    if (k >= j && k < i) s += c[k] * W[tri(k, j)];
                }
                W[tri(i, j)] = -inv * s;
            }
        }
        W[tri(i, i)] = inv;

        // ---- Output row i = sum_{j<=i} W[i][j] * v_j ----
        float4 o = make_float4(0.0f, 0.0f, 0.0f, 0.0f);
#pragma unroll
        for (int j = 0; j < NE; j++) {
            if (j <= i) {
                float wj = W[tri(i, j)];
                o.x += wj * v[j].x;
                o.y += wj * v[j].y;
                o.z += wj * v[j].z;
                o.w += wj * v[j].w;
            }
        }
        xout[i * F4 + t] = o;
    }
}

extern "C" void kernel_launch(void* const* d_in, const int* in_sizes, int n_in,
                              void* d_out, int out_size) {
    const float* x = (const float*)d_in[0];
    float* out = (float*)d_out;
    const int batch = in_sizes[0] / (NE * DIM);  // 8192
    gram_gs_kernel<<<batch, NT>>>(x, out);
}

// round 3
// speedup vs baseline: 1.7666x; 1.5383x over previous
#include <cuda_runtime.h>

#define NE 8
#define DIM 1024
#define NT 256
#define F4 (DIM / 4)
#define NG 36        // lower triangle of 8x8 Gram
#define RW 129       // 128 partials per value, +1 pad for bank-conflict-free column reads

__device__ __forceinline__ constexpr int tri(int i, int j) { return i * (i + 1) / 2 + j; }

__global__ __launch_bounds__(NT, 3) void gram_gs_kernel(
    const float* __restrict__ x, float* __restrict__ out) {
    const int b = blockIdx.x;
    const int t = threadIdx.x;
    const int warp = t >> 5;
    const int lane = t & 31;

    __shared__ float red[NG][RW];  // 18.6 KB
    __shared__ float gf[NG];

    const float4* __restrict__ xin =
        reinterpret_cast<const float4*>(x + (size_t)b * NE * DIM);
    float4* __restrict__ xout =
        reinterpret_cast<float4*>(out + (size_t)b * NE * DIM);

    // ---- Load all 8 expert slices (coalesced LDG.128) ----
    float4 v[NE];
#pragma unroll
    for (int i = 0; i < NE; i++) v[i] = xin[i * F4 + t];

    // ---- Gram partials: 1-level shuffle, lanes 0-15 publish 128 partials/value ----
#pragma unroll
    for (int i = 0; i < NE; i++) {
#pragma unroll
        for (int j = 0; j <= i; j++) {
            float s = v[i].x * v[j].x + v[i].y * v[j].y +
                      v[i].z * v[j].z + v[i].w * v[j].w;
            s += __shfl_xor_sync(0xffffffffu, s, 16);
            if (lane < 16) red[tri(i, j)][warp * 16 + lane] = s;
        }
    }
    __syncthreads();

    // ---- Final reduce: threads 0..35 each sum 128 partials (conflict-free via pad) ----
    if (t < NG) {
        float s0 = 0.f, s1 = 0.f, s2 = 0.f, s3 = 0.f;
#pragma unroll
        for (int m = 0; m < 128; m += 4) {
            s0 += red[t][m + 0];
            s1 += red[t][m + 1];
            s2 += red[t][m + 2];
            s3 += red[t][m + 3];
        }
        gf[t] = (s0 + s1) + (s2 + s3);
    }
    __syncthreads();

    // ---- Gram-Schmidt in coefficient space; W in regs, g read from smem (broadcast) ----
    float W[NG];
    {
        float inv = rsqrtf(gf[0]);
        W[0] = inv;
        float4 o;
        o.x = inv * v[0].x; o.y = inv * v[0].y;
        o.z = inv * v[0].z; o.w = inv * v[0].w;
        xout[t] = o;
    }

#pragma unroll
    for (int i = 1; i < NE; i++) {
        // Pull Gram row i from smem once (broadcast LDS).
        float gi[NE];
#pragma unroll
        for (int j = 0; j < NE; j++) {
            if (j <= i) gi[j] = gf[tri(i, j)];
        }
        // c_k = x_i . basis_k = sum_{j<=k} W[k][j] * G[i][j]
        float c[NE - 1];
#pragma unroll
        for (int k = 0; k < NE - 1; k++) {
            if (k < i) {
                float s = 0.f;
#pragma unroll
                for (int j = 0; j < NE - 1; j++) {
                    if (j <= k) s += W[tri(k, j)] * gi[j];
                }
                c[k] = s;
            }
        }
        // ||w||^2 = G_ii - sum c_k^2
        float n2 = gi[i];
#pragma unroll
        for (int k = 0; k < NE - 1; k++) {
            if (k < i) n2 -= c[k] * c[k];
        }
        float inv = rsqrtf(n2);
        // W[i][j] = -inv * sum_{k=j..i-1} c_k W[k][j];  W[i][i] = inv
#pragma unroll
        for (int j = 0; j < NE - 1; j++) {
            if (j < i) {
                float s = 0.f;
#pragma unroll
                for (int k = 0; k < NE - 1; k++) {
                    if (k >= j && k < i) s += c[k] * W[tri(k, j)];
                }
                W[tri(i, j)] = -inv * s;
            }
        }
        W[tri(i, i)] = inv;

        // Fused output row i = sum_{j<=i} W[i][j] * v_j
        float4 o = make_float4(0.f, 0.f, 0.f, 0.f);
#pragma unroll
        for (int j = 0; j < NE; j++) {
            if (j <= i) {
                float wj = W[tri(i, j)];
                o.x += wj * v[j].x;
                o.y += wj * v[j].y;
                o.z += wj * v[j].z;
                o.w += wj * v[j].w;
            }
        }
        xout[i * F4 + t] = o;
    }
}

extern "C" void kernel_launch(void* const* d_in, const int* in_sizes, int n_in,
                              void* d_out, int out_size) {
    const float* x = (const float*)d_in[0];
    float* out = (float*)d_out;
    const int batch = in_sizes[0] / (NE * DIM);  // 8192
    gram_gs_kernel<<<batch, NT>>>(x, out);
}